// round 16
// baseline (speedup 1.0000x reference)
#include <cuda_runtime.h>
#include <math.h>
#include <stdint.h>

#define Tn   512
#define Bn   64
#define OBSn 512
#define Hn   1024
#define An   18
#define G4n  4096
#define Mn   32768   // Tn*Bn

// ---------------- scratch (device globals; no runtime allocation) ----------------
__device__ float g_enc   [(size_t)Mn * Hn];       // encoded, tf32 bits  (128 MB)
__device__ float g_xg    [(size_t)Tn * G4n * Bn]; // x_gates [t][g][b]   (512 MB)
__device__ float g_lat   [(size_t)Tn * Hn * Bn];  // latent  [t][h][b]   (128 MB)
__device__ float g_obs_t [(size_t)Mn * OBSn];     // obs, tf32 bits      (64 MB)
__device__ float g_wenc_t[(size_t)Hn * OBSn];     // W_enc tf32 bits
__device__ unsigned g_bar_count;
__device__ unsigned g_bar_gen;

__device__ __forceinline__ unsigned f2tf32(float x) {
    unsigned r;
    asm("cvt.rna.tf32.f32 %0, %1;" : "=r"(r) : "f"(x));
    return r;
}
__device__ __forceinline__ uint32_t smem_u32(const void* p) {
    uint32_t a;
    asm("{ .reg .u64 t; cvta.to.shared.u64 t, %1; cvt.u32.u64 %0, t; }" : "=r"(a) : "l"(p));
    return a;
}
__device__ __forceinline__ void cp16(uint32_t dst, const void* src) {
    asm volatile("cp.async.cg.shared.global [%0], [%1], 16;" :: "r"(dst), "l"(src));
}
#define CP_COMMIT() asm volatile("cp.async.commit_group;" ::: "memory")
#define CP_WAIT2()  asm volatile("cp.async.wait_group 2;" ::: "memory")

// =====================================================================
// GEMM1: cp.async 4-stage pipeline, KDIM=512 (measured 251-389us, keep).
// Out[m][Hn] = tf32(relu(acc + bias1[n]))
// =====================================================================
#define STG_W  2560
#define STG_B  10240
#define BOFF_B 40960

template<int KDIM>
__global__ void __launch_bounds__(256, 2) cp_gemm1(
    const float* __restrict__ A, const float* __restrict__ Bm,
    const float* __restrict__ bias1, float* __restrict__ Out)
{
    extern __shared__ unsigned smp[];
    __shared__ float biasS[128];
    const int tid  = threadIdx.x;
    const int wid  = tid >> 5, lane = tid & 31;
    const int wr   = wid >> 1, wc = wid & 1;
    const int gq   = lane >> 2, tg = lane & 3;
    const int bm   = blockIdx.y << 7;
    const int bn   = blockIdx.x << 7;
    const int lr   = tid >> 2;
    const int lk   = (tid & 3) << 2;
    constexpr int NK = KDIM / 16;

    if (tid < 128) biasS[tid] = bias1[bn + tid];

    const float* Ap = A  + (size_t)(bm + lr) * KDIM + lk;
    const float* Bp = Bm + (size_t)(bn + lr) * KDIM + lk;
    const uint32_t aAddr = smem_u32(smp) + (uint32_t)(lr * 20 + lk) * 4;
    const uint32_t bAddr = aAddr + BOFF_B;
    const uint32_t rowOff = 64 * 20 * 4;

#pragma unroll
    for (int s = 0; s < 3; s++) {
        const uint32_t so = (uint32_t)(s & 3) * STG_B;
        cp16(aAddr + so,          Ap + (size_t)s * 16);
        cp16(aAddr + so + rowOff, Ap + (size_t)64 * KDIM + s * 16);
        cp16(bAddr + so,          Bp + (size_t)s * 16);
        cp16(bAddr + so + rowOff, Bp + (size_t)64 * KDIM + s * 16);
        CP_COMMIT();
    }

    float acc[16][4];
#pragma unroll
    for (int t = 0; t < 16; t++)
#pragma unroll
        for (int e = 0; e < 4; e++) acc[t][e] = 0.f;

    for (int kt = 0; kt < NK; kt++) {
        CP_WAIT2();
        __syncthreads();
        {
            const int s = kt + 3;
            if (s < NK) {
                const uint32_t so = (uint32_t)(s & 3) * STG_B;
                cp16(aAddr + so,          Ap + (size_t)s * 16);
                cp16(aAddr + so + rowOff, Ap + (size_t)64 * KDIM + s * 16);
                cp16(bAddr + so,          Bp + (size_t)s * 16);
                cp16(bAddr + so + rowOff, Bp + (size_t)64 * KDIM + s * 16);
            }
            CP_COMMIT();
        }
        const unsigned* Asl = smp + (kt & 3) * STG_W;
        const unsigned* Bsl = smp + (BOFF_B / 4) + (kt & 3) * STG_W;
#pragma unroll
        for (int ks = 0; ks < 2; ks++) {
            const int kf = ks << 3;
            unsigned af[2][4], bf[8][2];
#pragma unroll
            for (int i = 0; i < 2; i++) {
                const int mr = (wr << 5) + (i << 4) + gq;
                af[i][0] = Asl[mr * 20 + kf + tg];
                af[i][1] = Asl[(mr + 8) * 20 + kf + tg];
                af[i][2] = Asl[mr * 20 + kf + tg + 4];
                af[i][3] = Asl[(mr + 8) * 20 + kf + tg + 4];
            }
#pragma unroll
            for (int j = 0; j < 8; j++) {
                const int nn = (wc << 6) + (j << 3) + gq;
                bf[j][0] = Bsl[nn * 20 + kf + tg];
                bf[j][1] = Bsl[nn * 20 + kf + tg + 4];
            }
#pragma unroll
            for (int i = 0; i < 2; i++)
#pragma unroll
                for (int j = 0; j < 8; j++) {
                    float* c = acc[i * 8 + j];
                    asm volatile(
                        "mma.sync.aligned.m16n8k8.row.col.f32.tf32.tf32.f32 "
                        "{%0,%1,%2,%3}, {%4,%5,%6,%7}, {%8,%9}, {%0,%1,%2,%3};"
                        : "+f"(c[0]), "+f"(c[1]), "+f"(c[2]), "+f"(c[3])
                        : "r"(af[i][0]), "r"(af[i][1]), "r"(af[i][2]), "r"(af[i][3]),
                          "r"(bf[j][0]), "r"(bf[j][1]));
                }
        }
    }

#pragma unroll
    for (int i = 0; i < 2; i++) {
#pragma unroll
        for (int j = 0; j < 8; j++) {
            const int r0 = bm + (wr << 5) + (i << 4) + gq;
            const int cl = (wc << 6) + (j << 3) + (tg << 1);
            const float bv0 = biasS[cl], bv1 = biasS[cl + 1];
            const float* c = acc[i * 8 + j];
            float2 o0, o1;
            o0.x = __uint_as_float(f2tf32(fmaxf(c[0] + bv0, 0.f)));
            o0.y = __uint_as_float(f2tf32(fmaxf(c[1] + bv1, 0.f)));
            o1.x = __uint_as_float(f2tf32(fmaxf(c[2] + bv0, 0.f)));
            o1.y = __uint_as_float(f2tf32(fmaxf(c[3] + bv1, 0.f)));
            *(float2*)(Out + (size_t)r0 * Hn + bn + cl)       = o0;
            *(float2*)(Out + (size_t)(r0 + 8) * Hn + bn + cl) = o1;
        }
    }
}

// =====================================================================
// GEMM2 (R13-proven LDG version): 64x64 warp tiles, 128 thr, 2-stage
// LDG->cvt->STS double buffer, pitch-20. Raw W_ih (cvt inline).
// XGST epilogue -> g_xg [t][n][b], m = t*64+b. K = Hn.
// =====================================================================
__global__ void __launch_bounds__(128, 2) g2_gemm(
    const float* __restrict__ A, const float* __restrict__ Bm,
    const float* __restrict__ bias1, const float* __restrict__ bias2)
{
    __shared__ unsigned As[2][128][20];
    __shared__ unsigned Bs[2][128][20];
    const int K = Hn;
    const int tid  = threadIdx.x;
    const int wid  = tid >> 5, lane = tid & 31;
    const int wr   = wid >> 1, wc = wid & 1;       // warp grid 2x2
    const int gq   = lane >> 2, tg = lane & 3;
    const int bm   = blockIdx.y << 7;
    const int bn   = blockIdx.x << 7;
    const int lr   = tid >> 2;                     // 0..31
    const int lk   = (tid & 3) << 2;               // 0,4,8,12

    const float* Ap = A  + (size_t)(bm + lr) * K + lk;
    const float* Bp = Bm + (size_t)(bn + lr) * K + lk;

    float4 pa[4], pb[4];
#pragma unroll
    for (int r = 0; r < 4; r++) {
        pa[r] = *(const float4*)(Ap + (size_t)(r << 5) * K);
        pb[r] = *(const float4*)(Bp + (size_t)(r << 5) * K);
    }

    float acc[32][4];
#pragma unroll
    for (int t = 0; t < 32; t++)
#pragma unroll
        for (int e = 0; e < 4; e++) acc[t][e] = 0.f;

    // stage 0
#pragma unroll
    for (int r = 0; r < 4; r++) {
        uint4 u;
        u.x = f2tf32(pa[r].x); u.y = f2tf32(pa[r].y); u.z = f2tf32(pa[r].z); u.w = f2tf32(pa[r].w);
        *(uint4*)&As[0][lr + (r << 5)][lk] = u;
        u.x = f2tf32(pb[r].x); u.y = f2tf32(pb[r].y); u.z = f2tf32(pb[r].z); u.w = f2tf32(pb[r].w);
        *(uint4*)&Bs[0][lr + (r << 5)][lk] = u;
    }
    __syncthreads();

    int p = 0;
    for (int k0 = 0; k0 < K; k0 += 16) {
        const bool more = (k0 + 16) < K;
        if (more) {
#pragma unroll
            for (int r = 0; r < 4; r++) {
                pa[r] = *(const float4*)(Ap + (size_t)(r << 5) * K + k0 + 16);
                pb[r] = *(const float4*)(Bp + (size_t)(r << 5) * K + k0 + 16);
            }
        }
#pragma unroll
        for (int ks = 0; ks < 2; ks++) {
            const int kf = ks << 3;
            unsigned af[4][4], bf[8][2];
#pragma unroll
            for (int i = 0; i < 4; i++) {
                const int mr = (wr << 6) + (i << 4) + gq;
                af[i][0] = As[p][mr][kf + tg];
                af[i][1] = As[p][mr + 8][kf + tg];
                af[i][2] = As[p][mr][kf + tg + 4];
                af[i][3] = As[p][mr + 8][kf + tg + 4];
            }
#pragma unroll
            for (int j = 0; j < 8; j++) {
                const int nn = (wc << 6) + (j << 3) + gq;
                bf[j][0] = Bs[p][nn][kf + tg];
                bf[j][1] = Bs[p][nn][kf + tg + 4];
            }
#pragma unroll
            for (int i = 0; i < 4; i++)
#pragma unroll
                for (int j = 0; j < 8; j++) {
                    float* c = acc[i * 8 + j];
                    asm volatile(
                        "mma.sync.aligned.m16n8k8.row.col.f32.tf32.tf32.f32 "
                        "{%0,%1,%2,%3}, {%4,%5,%6,%7}, {%8,%9}, {%0,%1,%2,%3};"
                        : "+f"(c[0]), "+f"(c[1]), "+f"(c[2]), "+f"(c[3])
                        : "r"(af[i][0]), "r"(af[i][1]), "r"(af[i][2]), "r"(af[i][3]),
                          "r"(bf[j][0]), "r"(bf[j][1]));
                }
        }
        if (more) {
            const int q = p ^ 1;
#pragma unroll
            for (int r = 0; r < 4; r++) {
                uint4 u;
                u.x = f2tf32(pa[r].x); u.y = f2tf32(pa[r].y); u.z = f2tf32(pa[r].z); u.w = f2tf32(pa[r].w);
                *(uint4*)&As[q][lr + (r << 5)][lk] = u;
                u.x = f2tf32(pb[r].x); u.y = f2tf32(pb[r].y); u.z = f2tf32(pb[r].z); u.w = f2tf32(pb[r].w);
                *(uint4*)&Bs[q][lr + (r << 5)][lk] = u;
            }
            __syncthreads();
            p = q;
        }
    }

    // ---- epilogue: XGST -> g_xg[t][n][b] ----
#pragma unroll
    for (int i = 0; i < 4; i++) {
#pragma unroll
        for (int j = 0; j < 8; j++) {
            const int r0 = bm + (wr << 6) + (i << 4) + gq;
            const int cb = bn + (wc << 6) + (j << 3) + (tg << 1);
            const float bv0 = bias1[cb]     + bias2[cb];
            const float bv1 = bias1[cb + 1] + bias2[cb + 1];
            const float* c = acc[i * 8 + j];
            const float v00 = c[0] + bv0, v01 = c[1] + bv1;
            const float v10 = c[2] + bv0, v11 = c[3] + bv1;
            const int t0 = r0 >> 6, b0 = r0 & 63;
            const int t1 = (r0 + 8) >> 6, b1 = (r0 + 8) & 63;
            g_xg[((size_t)t0 * G4n + cb)     * Bn + b0] = v00;
            g_xg[((size_t)t0 * G4n + cb + 1) * Bn + b0] = v01;
            g_xg[((size_t)t1 * G4n + cb)     * Bn + b1] = v10;
            g_xg[((size_t)t1 * G4n + cb + 1) * Bn + b1] = v11;
        }
    }
}

// ---------------- elementwise fp32 -> tf32-bits ----------------
__global__ void cvt_tf32_kernel(const float4* __restrict__ src, float4* __restrict__ dst, int n4) {
    const int i = blockIdx.x * blockDim.x + threadIdx.x;
    if (i < n4) {
        const float4 v = src[i];
        float4 o;
        o.x = __uint_as_float(f2tf32(v.x));
        o.y = __uint_as_float(f2tf32(v.y));
        o.z = __uint_as_float(f2tf32(v.z));
        o.w = __uint_as_float(f2tf32(v.w));
        dst[i] = o;
    }
}

// =====================================================================
// Persistent LSTM scan (R12-proven pipeline) + NEW: x_gates prefetch for
// step t+1 hoisted BEFORE the grid-barrier spin (DRAM latency hidden
// behind barrier wait instead of exposed at step start).
// =====================================================================
#define WS_PITCH 1028
#define HS_PITCH 72
#define HS_BUF   (128 * HS_PITCH)
#define RED_PITCH 66

__device__ __forceinline__ float sigf(float x) { return 1.f / (1.f + __expf(-x)); }

__global__ void __launch_bounds__(256, 1) lstm_kernel(
    const float* __restrict__ W_hh, const float* __restrict__ mask,
    float* __restrict__ out_h, float* __restrict__ out_c, int nblk)
{
    extern __shared__ unsigned smu[];
    unsigned* Ws = smu;
    unsigned* hs = smu + 32 * WS_PITCH;
    float*   red = (float*)hs;

    const int tid  = threadIdx.x;
    const int wid  = tid >> 5, lane = tid & 31;
    const int gq   = lane >> 2, tg = lane & 3;
    const int j0   = blockIdx.x << 3;

    for (int i = tid; i < 32 * 256; i += 256) {
        const int r  = i >> 8;
        const int kq = (i & 255) << 2;
        const int grow = ((r >> 3) << 10) + j0 + (r & 7);
        const float4 w = *(const float4*)(W_hh + (size_t)grow * Hn + kq);
        uint4 u;
        u.x = f2tf32(w.x); u.y = f2tf32(w.y); u.z = f2tf32(w.z); u.w = f2tf32(w.w);
        *(uint4*)&Ws[r * WS_PITCH + kq] = u;
    }

    const int jjA = tid >> 6;
    const int jjB = (tid >> 6) + 4;
    const int bb  = tid & 63;

    float c0r = 0.f, c1r = 0.f;
    unsigned gen = 0;
    if (tid == 0) gen = *(volatile unsigned*)&g_bar_gen;

    // prefetch x_gates for t=0
    float xq[2][4];
#pragma unroll
    for (int q = 0; q < 4; q++) {
        xq[0][q] = __ldcg(g_xg + ((q << 10) + j0 + jjA) * Bn + bb);
        xq[1][q] = __ldcg(g_xg + ((q << 10) + j0 + jjB) * Bn + bb);
    }
    __syncthreads();

    for (int t = 0; t < Tn; t++) {
        if (t > 0) {
            float acc[16][4];
#pragma unroll
            for (int q = 0; q < 16; q++)
#pragma unroll
                for (int e = 0; e < 4; e++) acc[q][e] = 0.f;

            const float* Hp = g_lat + (size_t)(t - 1) * (Hn * Bn);
            float4 ld[8];

#pragma unroll
            for (int ii = 0; ii < 8; ii++) {
                const int e4 = tid + (ii << 8);
                const int k  = e4 >> 4;
                const int b  = (e4 & 15) << 2;
                ld[ii] = __ldcg((const float4*)(Hp + ((size_t)k << 6) + b));
            }
#pragma unroll
            for (int ii = 0; ii < 8; ii++) {
                const int e4 = tid + (ii << 8);
                const int k  = e4 >> 4;
                const int b  = (e4 & 15) << 2;
                uint4 u;
                u.x = f2tf32(ld[ii].x); u.y = f2tf32(ld[ii].y);
                u.z = f2tf32(ld[ii].z); u.w = f2tf32(ld[ii].w);
                *(uint4*)&hs[k * HS_PITCH + b] = u;
            }
            __syncthreads();

#pragma unroll 2
            for (int cc = 0; cc < 8; cc++) {
                if (cc < 7) {
#pragma unroll
                    for (int ii = 0; ii < 8; ii++) {
                        const int e4 = tid + (ii << 8);
                        const int k  = e4 >> 4;
                        const int b  = (e4 & 15) << 2;
                        ld[ii] = __ldcg((const float4*)(Hp + (((size_t)((cc + 1) << 7) + k) << 6) + b));
                    }
                }

                const unsigned* hb = hs + (cc & 1) * HS_BUF;
#pragma unroll
                for (int s = 0; s < 2; s++) {
                    const int kl = (wid << 4) + (s << 3);
                    const int kg = (cc << 7) + kl;
                    unsigned af[2][4], bf[8][2];
#pragma unroll
                    for (int i = 0; i < 2; i++) {
                        const int r = (i << 4) + gq;
                        af[i][0] = Ws[r * WS_PITCH + kg + tg];
                        af[i][1] = Ws[(r + 8) * WS_PITCH + kg + tg];
                        af[i][2] = Ws[r * WS_PITCH + kg + tg + 4];
                        af[i][3] = Ws[(r + 8) * WS_PITCH + kg + tg + 4];
                    }
#pragma unroll
                    for (int j = 0; j < 8; j++) {
                        bf[j][0] = hb[(kl + tg) * HS_PITCH + (j << 3) + gq];
                        bf[j][1] = hb[(kl + tg + 4) * HS_PITCH + (j << 3) + gq];
                    }
#pragma unroll
                    for (int i = 0; i < 2; i++)
#pragma unroll
                        for (int j = 0; j < 8; j++) {
                            float* c = acc[i * 8 + j];
                            asm volatile(
                                "mma.sync.aligned.m16n8k8.row.col.f32.tf32.tf32.f32 "
                                "{%0,%1,%2,%3}, {%4,%5,%6,%7}, {%8,%9}, {%0,%1,%2,%3};"
                                : "+f"(c[0]), "+f"(c[1]), "+f"(c[2]), "+f"(c[3])
                                : "r"(af[i][0]), "r"(af[i][1]), "r"(af[i][2]), "r"(af[i][3]),
                                  "r"(bf[j][0]), "r"(bf[j][1]));
                        }
                }

                if (cc < 7) {
                    unsigned* ho = hs + ((cc + 1) & 1) * HS_BUF;
#pragma unroll
                    for (int ii = 0; ii < 8; ii++) {
                        const int e4 = tid + (ii << 8);
                        const int k  = e4 >> 4;
                        const int b  = (e4 & 15) << 2;
                        uint4 u;
                        u.x = f2tf32(ld[ii].x); u.y = f2tf32(ld[ii].y);
                        u.z = f2tf32(ld[ii].z); u.w = f2tf32(ld[ii].w);
                        *(uint4*)&ho[k * HS_PITCH + b] = u;
                    }
                }
                __syncthreads();
            }

#pragma unroll
            for (int i = 0; i < 2; i++)
#pragma unroll
                for (int j = 0; j < 8; j++) {
                    const float* c = acc[i * 8 + j];
                    const int r = (i << 4) + gq;
                    const int b = (j << 3) + (tg << 1);
                    *(float2*)&red[((wid << 5) + r) * RED_PITCH + b]     = make_float2(c[0], c[1]);
                    *(float2*)&red[((wid << 5) + r + 8) * RED_PITCH + b] = make_float2(c[2], c[3]);
                }
            __syncthreads();

#pragma unroll
            for (int pp = 0; pp < 2; pp++) {
                const int jj = pp ? jjB : jjA;
                float gate[4];
#pragma unroll
                for (int q = 0; q < 4; q++) {
                    const int r = (q << 3) + (jj & 7);
                    float s = xq[pp][q];
#pragma unroll
                    for (int w8 = 0; w8 < 8; w8++)
                        s += red[((w8 << 5) + r) * RED_PITCH + bb];
                    gate[q] = s;
                }
                const float cprev = pp ? c1r : c0r;
                float cn = sigf(gate[1]) * cprev + sigf(gate[0]) * tanhf(gate[2]);
                float hn = sigf(gate[3]) * tanhf(cn);
                const float m = mask[t * Bn + bb];
                hn *= m; cn *= m;
                if (pp) c1r = cn; else c0r = cn;
                g_lat[(size_t)t * (Hn * Bn) + ((size_t)(j0 + (jj & 7)) << 6) + bb] = hn;
                if (t == Tn - 1) {
                    out_h[bb * Hn + j0 + (jj & 7)] = hn;
                    out_c[bb * Hn + j0 + (jj & 7)] = cn;
                }
            }
        } else {
#pragma unroll
            for (int pp = 0; pp < 2; pp++) {
                const int jj = (pp ? jjB : jjA) & 7;
                const float cprev = pp ? c1r : c0r;
                float cn = sigf(xq[pp][1]) * cprev + sigf(xq[pp][0]) * tanhf(xq[pp][2]);
                float hn = sigf(xq[pp][3]) * tanhf(cn);
                const float m = mask[t * Bn + bb];
                hn *= m; cn *= m;
                if (pp) c1r = cn; else c0r = cn;
                g_lat[(size_t)t * (Hn * Bn) + ((size_t)(j0 + jj) << 6) + bb] = hn;
            }
        }

        // ---- prefetch x_gates for t+1 (constant data; latency hidden by barrier) ----
        if (t + 1 < Tn) {
            const float* xgn = g_xg + (size_t)(t + 1) * (G4n * Bn);
#pragma unroll
            for (int q = 0; q < 4; q++) {
                xq[0][q] = __ldcg(xgn + ((q << 10) + j0 + jjA) * Bn + bb);
                xq[1][q] = __ldcg(xgn + ((q << 10) + j0 + jjB) * Bn + bb);
            }
        }

        // ---- grid barrier (sense-reversing generation counter) ----
        __threadfence();
        __syncthreads();
        if (tid == 0) {
            const unsigned arr = atomicAdd(&g_bar_count, 1);
            if (arr == (unsigned)(nblk - 1)) {
                atomicExch(&g_bar_count, 0);
                __threadfence();
                atomicAdd(&g_bar_gen, 1);
            } else {
                while (*(volatile unsigned*)&g_bar_gen == gen) { }
            }
            gen++;
            __threadfence();
        }
        __syncthreads();
    }
}

// =====================================================================
// Decoder (unchanged)
// =====================================================================
__global__ void __launch_bounds__(256, 1) decoder_kernel(
    const float* __restrict__ Wd, const float* __restrict__ bd,
    const float* __restrict__ mask, float* __restrict__ out_values)
{
    extern __shared__ float dsm[];
    float* Wds  = dsm;
    float* red2 = dsm + 18 * 1024;
    const int t = blockIdx.x;
    const int tid = threadIdx.x;

    for (int i = tid; i < (18 * 1024) / 4; i += 256)
        ((float4*)Wds)[i] = ((const float4*)Wd)[i];
    __syncthreads();

    const int s = tid >> 6;
    const int b = tid & 63;
    float acc[18];
#pragma unroll
    for (int a = 0; a < 18; a++) acc[a] = 0.f;

    const float* L = g_lat + (size_t)t * (Hn * Bn);
    const int hend = (s + 1) << 8;
    for (int h = s << 8; h < hend; h++) {
        const float x = __ldcg(L + (h << 6) + b);
#pragma unroll
        for (int a = 0; a < 18; a++)
            acc[a] = fmaf(x, Wds[a * 1024 + h], acc[a]);
    }
#pragma unroll
    for (int a = 0; a < 18; a++) red2[(s * 64 + b) * 18 + a] = acc[a];
    __syncthreads();

    for (int o = tid; o < 64 * 18; o += 256) {
        const int b2 = o / 18;
        const int a  = o - b2 * 18;
        float v = red2[b2 * 18 + a] + red2[(64 + b2) * 18 + a]
                + red2[(128 + b2) * 18 + a] + red2[(192 + b2) * 18 + a];
        v = (v + bd[a]) * mask[t * Bn + b2];
        out_values[(size_t)t * (Bn * An) + o] = v;
    }
}

// =====================================================================
extern "C" void kernel_launch(void* const* d_in, const int* in_sizes, int n_in,
                              void* d_out, int out_size)
{
    const float* obs   = (const float*)d_in[0];
    const float* mask  = (const float*)d_in[1];
    const float* W_enc = (const float*)d_in[2];
    const float* b_enc = (const float*)d_in[3];
    const float* W_ih  = (const float*)d_in[4];
    const float* b_ih  = (const float*)d_in[5];
    const float* W_hh  = (const float*)d_in[6];
    const float* b_hh  = (const float*)d_in[7];
    const float* W_dec = (const float*)d_in[8];
    const float* b_dec = (const float*)d_in[9];

    float* out        = (float*)d_out;
    float* out_values = out;                                   // [512][64][18]
    float* out_h      = out + (size_t)Tn * Bn * An;            // [64][1024]
    float* out_c      = out_h + (size_t)Bn * Hn;               // [64][1024]

    float *enc_p, *obs_p, *wenc_p;
    cudaGetSymbolAddress((void**)&enc_p,  g_enc);
    cudaGetSymbolAddress((void**)&obs_p,  g_obs_t);
    cudaGetSymbolAddress((void**)&wenc_p, g_wenc_t);

    const int gemm1_smem = 81920;
    const int lstm_smem  = (32 * WS_PITCH + 2 * HS_BUF) * 4;   // 205312 B
    cudaFuncSetAttribute(cp_gemm1<OBSn>, cudaFuncAttributeMaxDynamicSharedMemorySize, gemm1_smem);
    cudaFuncSetAttribute(lstm_kernel,    cudaFuncAttributeMaxDynamicSharedMemorySize, lstm_smem);
    cudaFuncSetAttribute(decoder_kernel, cudaFuncAttributeMaxDynamicSharedMemorySize, 92160);

    // 0) pre-convert GEMM1 inputs to tf32 bits (rna)
    cvt_tf32_kernel<<<(Mn * OBSn / 4 + 255) / 256, 256>>>((const float4*)obs,   (float4*)obs_p,  Mn * OBSn / 4);
    cvt_tf32_kernel<<<(Hn * OBSn / 4 + 255) / 256, 256>>>((const float4*)W_enc, (float4*)wenc_p, Hn * OBSn / 4);

    // 1) encoded = tf32(relu(obs @ W_enc^T + b_enc)) -> g_enc (tf32 bits)
    dim3 g1(Hn / 128, Mn / 128);
    cp_gemm1<OBSn><<<g1, 256, gemm1_smem>>>(obs_p, wenc_p, b_enc, enc_p);

    // 2) x_gates = enc @ W_ih^T + b_ih + b_hh -> g_xg [t][g][b]
    //    (R13 LDG version, raw W_ih; k-order identical -> bitwise-same x_gates)
    dim3 g2(G4n / 128, Mn / 128);
    g2_gemm<<<g2, 128>>>(enc_p, W_ih, b_ih, b_hh);

    // 3) persistent LSTM scan -> g_lat, out_h, out_c
    lstm_kernel<<<128, 256, lstm_smem>>>(W_hh, mask, out_h, out_c, 128);

    // 4) decoder -> out_values
    decoder_kernel<<<Tn, 256, 92160>>>(W_dec, b_dec, mask, out_values);
}

// round 17
// speedup vs baseline: 1.4688x; 1.4688x over previous
#include <cuda_runtime.h>
#include <math.h>
#include <stdint.h>

#define Tn   512
#define Bn   64
#define OBSn 512
#define Hn   1024
#define An   18
#define G4n  4096
#define Mn   32768   // Tn*Bn

// ---------------- scratch (device globals; no runtime allocation) ----------------
__device__ float g_enc   [(size_t)Mn * Hn];       // encoded, tf32 bits  (128 MB)
__device__ float g_xg    [(size_t)Tn * G4n * Bn]; // x_gates [t][g][b]   (512 MB)
__device__ float g_lat   [(size_t)Tn * Hn * Bn];  // latent  [t][h][b]   (128 MB)
__device__ float g_obs_t [(size_t)Mn * OBSn];     // obs, tf32 bits      (64 MB)
__device__ float g_wenc_t[(size_t)Hn * OBSn];     // W_enc tf32 bits
__device__ float g_wih_t [(size_t)G4n * Hn];      // W_ih tf32 bits (16 MB)
__device__ unsigned g_bar_count;
__device__ unsigned g_bar_gen;

__device__ __forceinline__ unsigned f2tf32(float x) {
    unsigned r;
    asm("cvt.rna.tf32.f32 %0, %1;" : "=r"(r) : "f"(x));
    return r;
}
__device__ __forceinline__ uint32_t smem_u32(const void* p) {
    uint32_t a;
    asm("{ .reg .u64 t; cvta.to.shared.u64 t, %1; cvt.u32.u64 %0, t; }" : "=r"(a) : "l"(p));
    return a;
}
__device__ __forceinline__ void cp16(uint32_t dst, const void* src) {
    asm volatile("cp.async.cg.shared.global [%0], [%1], 16;" :: "r"(dst), "l"(src));
}
#define CP_COMMIT() asm volatile("cp.async.commit_group;" ::: "memory")
#define CP_WAIT2()  asm volatile("cp.async.wait_group 2;" ::: "memory")

// =====================================================================
// GEMM1: cp.async 4-stage pipeline, KDIM=512 (measured 251-389us, keep).
// Out[m][Hn] = tf32(relu(acc + bias1[n]))
// =====================================================================
#define STG_W  2560
#define STG_B  10240
#define BOFF_B 40960

template<int KDIM>
__global__ void __launch_bounds__(256, 2) cp_gemm1(
    const float* __restrict__ A, const float* __restrict__ Bm,
    const float* __restrict__ bias1, float* __restrict__ Out)
{
    extern __shared__ unsigned smp[];
    __shared__ float biasS[128];
    const int tid  = threadIdx.x;
    const int wid  = tid >> 5, lane = tid & 31;
    const int wr   = wid >> 1, wc = wid & 1;
    const int gq   = lane >> 2, tg = lane & 3;
    const int bm   = blockIdx.y << 7;
    const int bn   = blockIdx.x << 7;
    const int lr   = tid >> 2;
    const int lk   = (tid & 3) << 2;
    constexpr int NK = KDIM / 16;

    if (tid < 128) biasS[tid] = bias1[bn + tid];

    const float* Ap = A  + (size_t)(bm + lr) * KDIM + lk;
    const float* Bp = Bm + (size_t)(bn + lr) * KDIM + lk;
    const uint32_t aAddr = smem_u32(smp) + (uint32_t)(lr * 20 + lk) * 4;
    const uint32_t bAddr = aAddr + BOFF_B;
    const uint32_t rowOff = 64 * 20 * 4;

#pragma unroll
    for (int s = 0; s < 3; s++) {
        const uint32_t so = (uint32_t)(s & 3) * STG_B;
        cp16(aAddr + so,          Ap + (size_t)s * 16);
        cp16(aAddr + so + rowOff, Ap + (size_t)64 * KDIM + s * 16);
        cp16(bAddr + so,          Bp + (size_t)s * 16);
        cp16(bAddr + so + rowOff, Bp + (size_t)64 * KDIM + s * 16);
        CP_COMMIT();
    }

    float acc[16][4];
#pragma unroll
    for (int t = 0; t < 16; t++)
#pragma unroll
        for (int e = 0; e < 4; e++) acc[t][e] = 0.f;

    for (int kt = 0; kt < NK; kt++) {
        CP_WAIT2();
        __syncthreads();
        {
            const int s = kt + 3;
            if (s < NK) {
                const uint32_t so = (uint32_t)(s & 3) * STG_B;
                cp16(aAddr + so,          Ap + (size_t)s * 16);
                cp16(aAddr + so + rowOff, Ap + (size_t)64 * KDIM + s * 16);
                cp16(bAddr + so,          Bp + (size_t)s * 16);
                cp16(bAddr + so + rowOff, Bp + (size_t)64 * KDIM + s * 16);
            }
            CP_COMMIT();
        }
        const unsigned* Asl = smp + (kt & 3) * STG_W;
        const unsigned* Bsl = smp + (BOFF_B / 4) + (kt & 3) * STG_W;
#pragma unroll
        for (int ks = 0; ks < 2; ks++) {
            const int kf = ks << 3;
            unsigned af[2][4], bf[8][2];
#pragma unroll
            for (int i = 0; i < 2; i++) {
                const int mr = (wr << 5) + (i << 4) + gq;
                af[i][0] = Asl[mr * 20 + kf + tg];
                af[i][1] = Asl[(mr + 8) * 20 + kf + tg];
                af[i][2] = Asl[mr * 20 + kf + tg + 4];
                af[i][3] = Asl[(mr + 8) * 20 + kf + tg + 4];
            }
#pragma unroll
            for (int j = 0; j < 8; j++) {
                const int nn = (wc << 6) + (j << 3) + gq;
                bf[j][0] = Bsl[nn * 20 + kf + tg];
                bf[j][1] = Bsl[nn * 20 + kf + tg + 4];
            }
#pragma unroll
            for (int i = 0; i < 2; i++)
#pragma unroll
                for (int j = 0; j < 8; j++) {
                    float* c = acc[i * 8 + j];
                    asm volatile(
                        "mma.sync.aligned.m16n8k8.row.col.f32.tf32.tf32.f32 "
                        "{%0,%1,%2,%3}, {%4,%5,%6,%7}, {%8,%9}, {%0,%1,%2,%3};"
                        : "+f"(c[0]), "+f"(c[1]), "+f"(c[2]), "+f"(c[3])
                        : "r"(af[i][0]), "r"(af[i][1]), "r"(af[i][2]), "r"(af[i][3]),
                          "r"(bf[j][0]), "r"(bf[j][1]));
                }
        }
    }

#pragma unroll
    for (int i = 0; i < 2; i++) {
#pragma unroll
        for (int j = 0; j < 8; j++) {
            const int r0 = bm + (wr << 5) + (i << 4) + gq;
            const int cl = (wc << 6) + (j << 3) + (tg << 1);
            const float bv0 = biasS[cl], bv1 = biasS[cl + 1];
            const float* c = acc[i * 8 + j];
            float2 o0, o1;
            o0.x = __uint_as_float(f2tf32(fmaxf(c[0] + bv0, 0.f)));
            o0.y = __uint_as_float(f2tf32(fmaxf(c[1] + bv1, 0.f)));
            o1.x = __uint_as_float(f2tf32(fmaxf(c[2] + bv0, 0.f)));
            o1.y = __uint_as_float(f2tf32(fmaxf(c[3] + bv1, 0.f)));
            *(float2*)(Out + (size_t)r0 * Hn + bn + cl)       = o0;
            *(float2*)(Out + (size_t)(r0 + 8) * Hn + bn + cl) = o1;
        }
    }
}

// =====================================================================
// GEMM2 (R14 config, measured best): 64x64 warp tiles (4 warps, 128 thr)
// + cp.async.cg 4-stage staging. Inputs hold tf32 bits. Same fragment
// math / pitch-20 / k-order -> bitwise-identical x_gates.
// XGST epilogue -> g_xg[t][n][b].
// =====================================================================
__global__ void __launch_bounds__(128, 2) g2_gemm(
    const float* __restrict__ A, const float* __restrict__ Bm,
    const float* __restrict__ bias1, const float* __restrict__ bias2)
{
    extern __shared__ unsigned smp[];          // [4 stages][128][20] A, then B
    constexpr int K  = Hn;
    constexpr int NK = K / 16;                 // 64
    const int tid  = threadIdx.x;
    const int wid  = tid >> 5, lane = tid & 31;
    const int wr   = wid >> 1, wc = wid & 1;   // warp grid 2x2
    const int gq   = lane >> 2, tg = lane & 3;
    const int bm   = blockIdx.y << 7;
    const int bn   = blockIdx.x << 7;
    const int lr   = tid >> 2;                 // 0..31
    const int lk   = (tid & 3) << 2;           // 0,4,8,12

    const float* Ap = A  + (size_t)(bm + lr) * K + lk;
    const float* Bp = Bm + (size_t)(bn + lr) * K + lk;
    const uint32_t aAddr = smem_u32(smp) + (uint32_t)(lr * 20 + lk) * 4;
    const uint32_t bAddr = aAddr + BOFF_B;
    const uint32_t rowOff = 32 * 20 * 4;       // +32 rows within a stage

#pragma unroll
    for (int s = 0; s < 3; s++) {
        const uint32_t so = (uint32_t)s * STG_B;
#pragma unroll
        for (int r = 0; r < 4; r++) {
            cp16(aAddr + so + r * rowOff, Ap + (size_t)(r << 5) * K + s * 16);
            cp16(bAddr + so + r * rowOff, Bp + (size_t)(r << 5) * K + s * 16);
        }
        CP_COMMIT();
    }

    float acc[32][4];
#pragma unroll
    for (int t = 0; t < 32; t++)
#pragma unroll
        for (int e = 0; e < 4; e++) acc[t][e] = 0.f;

    for (int kt = 0; kt < NK; kt++) {
        CP_WAIT2();
        __syncthreads();
        {
            const int s = kt + 3;
            if (s < NK) {
                const uint32_t so = (uint32_t)(s & 3) * STG_B;
#pragma unroll
                for (int r = 0; r < 4; r++) {
                    cp16(aAddr + so + r * rowOff, Ap + (size_t)(r << 5) * K + s * 16);
                    cp16(bAddr + so + r * rowOff, Bp + (size_t)(r << 5) * K + s * 16);
                }
            }
            CP_COMMIT();
        }
        const unsigned* Asl = smp + (kt & 3) * STG_W;
        const unsigned* Bsl = smp + (BOFF_B / 4) + (kt & 3) * STG_W;
#pragma unroll
        for (int ks = 0; ks < 2; ks++) {
            const int kf = ks << 3;
            unsigned af[4][4], bf[8][2];
#pragma unroll
            for (int i = 0; i < 4; i++) {
                const int mr = (wr << 6) + (i << 4) + gq;
                af[i][0] = Asl[mr * 20 + kf + tg];
                af[i][1] = Asl[(mr + 8) * 20 + kf + tg];
                af[i][2] = Asl[mr * 20 + kf + tg + 4];
                af[i][3] = Asl[(mr + 8) * 20 + kf + tg + 4];
            }
#pragma unroll
            for (int j = 0; j < 8; j++) {
                const int nn = (wc << 6) + (j << 3) + gq;
                bf[j][0] = Bsl[nn * 20 + kf + tg];
                bf[j][1] = Bsl[nn * 20 + kf + tg + 4];
            }
#pragma unroll
            for (int i = 0; i < 4; i++)
#pragma unroll
                for (int j = 0; j < 8; j++) {
                    float* c = acc[i * 8 + j];
                    asm volatile(
                        "mma.sync.aligned.m16n8k8.row.col.f32.tf32.tf32.f32 "
                        "{%0,%1,%2,%3}, {%4,%5,%6,%7}, {%8,%9}, {%0,%1,%2,%3};"
                        : "+f"(c[0]), "+f"(c[1]), "+f"(c[2]), "+f"(c[3])
                        : "r"(af[i][0]), "r"(af[i][1]), "r"(af[i][2]), "r"(af[i][3]),
                          "r"(bf[j][0]), "r"(bf[j][1]));
                }
        }
    }

    // ---- epilogue: XGST -> g_xg[t][n][b] ----
#pragma unroll
    for (int i = 0; i < 4; i++) {
#pragma unroll
        for (int j = 0; j < 8; j++) {
            const int r0 = bm + (wr << 6) + (i << 4) + gq;
            const int cb = bn + (wc << 6) + (j << 3) + (tg << 1);
            const float bv0 = bias1[cb]     + bias2[cb];
            const float bv1 = bias1[cb + 1] + bias2[cb + 1];
            const float* c = acc[i * 8 + j];
            const float v00 = c[0] + bv0, v01 = c[1] + bv1;
            const float v10 = c[2] + bv0, v11 = c[3] + bv1;
            const int t0 = r0 >> 6, b0 = r0 & 63;
            const int t1 = (r0 + 8) >> 6, b1 = (r0 + 8) & 63;
            g_xg[((size_t)t0 * G4n + cb)     * Bn + b0] = v00;
            g_xg[((size_t)t0 * G4n + cb + 1) * Bn + b0] = v01;
            g_xg[((size_t)t1 * G4n + cb)     * Bn + b1] = v10;
            g_xg[((size_t)t1 * G4n + cb + 1) * Bn + b1] = v11;
        }
    }
}

// ---------------- elementwise fp32 -> tf32-bits ----------------
__global__ void cvt_tf32_kernel(const float4* __restrict__ src, float4* __restrict__ dst, int n4) {
    const int i = blockIdx.x * blockDim.x + threadIdx.x;
    if (i < n4) {
        const float4 v = src[i];
        float4 o;
        o.x = __uint_as_float(f2tf32(v.x));
        o.y = __uint_as_float(f2tf32(v.y));
        o.z = __uint_as_float(f2tf32(v.z));
        o.w = __uint_as_float(f2tf32(v.w));
        dst[i] = o;
    }
}

// =====================================================================
// Persistent LSTM scan (R12/R14-proven): double-buffered h chunks,
// xq prefetch AT STEP TOP (post-barrier, short live range — the R15/R16
// hoist across the barrier caused reg-pressure regression; do not repeat).
// =====================================================================
#define WS_PITCH 1028
#define HS_PITCH 72
#define HS_BUF   (128 * HS_PITCH)
#define RED_PITCH 66

__device__ __forceinline__ float sigf(float x) { return 1.f / (1.f + __expf(-x)); }

__global__ void __launch_bounds__(256, 1) lstm_kernel(
    const float* __restrict__ W_hh, const float* __restrict__ mask,
    float* __restrict__ out_h, float* __restrict__ out_c, int nblk)
{
    extern __shared__ unsigned smu[];
    unsigned* Ws = smu;
    unsigned* hs = smu + 32 * WS_PITCH;
    float*   red = (float*)hs;

    const int tid  = threadIdx.x;
    const int wid  = tid >> 5, lane = tid & 31;
    const int gq   = lane >> 2, tg = lane & 3;
    const int j0   = blockIdx.x << 3;

    for (int i = tid; i < 32 * 256; i += 256) {
        const int r  = i >> 8;
        const int kq = (i & 255) << 2;
        const int grow = ((r >> 3) << 10) + j0 + (r & 7);
        const float4 w = *(const float4*)(W_hh + (size_t)grow * Hn + kq);
        uint4 u;
        u.x = f2tf32(w.x); u.y = f2tf32(w.y); u.z = f2tf32(w.z); u.w = f2tf32(w.w);
        *(uint4*)&Ws[r * WS_PITCH + kq] = u;
    }

    const int jjA = tid >> 6;
    const int jjB = (tid >> 6) + 4;
    const int bb  = tid & 63;

    float c0r = 0.f, c1r = 0.f;
    unsigned gen = 0;
    if (tid == 0) gen = *(volatile unsigned*)&g_bar_gen;
    __syncthreads();

    for (int t = 0; t < Tn; t++) {
        float xq[2][4];
        const float* xgt = g_xg + (size_t)t * (G4n * Bn);
#pragma unroll
        for (int q = 0; q < 4; q++) {
            xq[0][q] = __ldcg(xgt + ((q << 10) + j0 + jjA) * Bn + bb);
            xq[1][q] = __ldcg(xgt + ((q << 10) + j0 + jjB) * Bn + bb);
        }

        if (t > 0) {
            float acc[16][4];
#pragma unroll
            for (int q = 0; q < 16; q++)
#pragma unroll
                for (int e = 0; e < 4; e++) acc[q][e] = 0.f;

            const float* Hp = g_lat + (size_t)(t - 1) * (Hn * Bn);
            float4 ld[8];

#pragma unroll
            for (int ii = 0; ii < 8; ii++) {
                const int e4 = tid + (ii << 8);
                const int k  = e4 >> 4;
                const int b  = (e4 & 15) << 2;
                ld[ii] = __ldcg((const float4*)(Hp + ((size_t)k << 6) + b));
            }
#pragma unroll
            for (int ii = 0; ii < 8; ii++) {
                const int e4 = tid + (ii << 8);
                const int k  = e4 >> 4;
                const int b  = (e4 & 15) << 2;
                uint4 u;
                u.x = f2tf32(ld[ii].x); u.y = f2tf32(ld[ii].y);
                u.z = f2tf32(ld[ii].z); u.w = f2tf32(ld[ii].w);
                *(uint4*)&hs[k * HS_PITCH + b] = u;
            }
            __syncthreads();

#pragma unroll 2
            for (int cc = 0; cc < 8; cc++) {
                if (cc < 7) {
#pragma unroll
                    for (int ii = 0; ii < 8; ii++) {
                        const int e4 = tid + (ii << 8);
                        const int k  = e4 >> 4;
                        const int b  = (e4 & 15) << 2;
                        ld[ii] = __ldcg((const float4*)(Hp + (((size_t)((cc + 1) << 7) + k) << 6) + b));
                    }
                }

                const unsigned* hb = hs + (cc & 1) * HS_BUF;
#pragma unroll
                for (int s = 0; s < 2; s++) {
                    const int kl = (wid << 4) + (s << 3);
                    const int kg = (cc << 7) + kl;
                    unsigned af[2][4], bf[8][2];
#pragma unroll
                    for (int i = 0; i < 2; i++) {
                        const int r = (i << 4) + gq;
                        af[i][0] = Ws[r * WS_PITCH + kg + tg];
                        af[i][1] = Ws[(r + 8) * WS_PITCH + kg + tg];
                        af[i][2] = Ws[r * WS_PITCH + kg + tg + 4];
                        af[i][3] = Ws[(r + 8) * WS_PITCH + kg + tg + 4];
                    }
#pragma unroll
                    for (int j = 0; j < 8; j++) {
                        bf[j][0] = hb[(kl + tg) * HS_PITCH + (j << 3) + gq];
                        bf[j][1] = hb[(kl + tg + 4) * HS_PITCH + (j << 3) + gq];
                    }
#pragma unroll
                    for (int i = 0; i < 2; i++)
#pragma unroll
                        for (int j = 0; j < 8; j++) {
                            float* c = acc[i * 8 + j];
                            asm volatile(
                                "mma.sync.aligned.m16n8k8.row.col.f32.tf32.tf32.f32 "
                                "{%0,%1,%2,%3}, {%4,%5,%6,%7}, {%8,%9}, {%0,%1,%2,%3};"
                                : "+f"(c[0]), "+f"(c[1]), "+f"(c[2]), "+f"(c[3])
                                : "r"(af[i][0]), "r"(af[i][1]), "r"(af[i][2]), "r"(af[i][3]),
                                  "r"(bf[j][0]), "r"(bf[j][1]));
                        }
                }

                if (cc < 7) {
                    unsigned* ho = hs + ((cc + 1) & 1) * HS_BUF;
#pragma unroll
                    for (int ii = 0; ii < 8; ii++) {
                        const int e4 = tid + (ii << 8);
                        const int k  = e4 >> 4;
                        const int b  = (e4 & 15) << 2;
                        uint4 u;
                        u.x = f2tf32(ld[ii].x); u.y = f2tf32(ld[ii].y);
                        u.z = f2tf32(ld[ii].z); u.w = f2tf32(ld[ii].w);
                        *(uint4*)&ho[k * HS_PITCH + b] = u;
                    }
                }
                __syncthreads();
            }

#pragma unroll
            for (int i = 0; i < 2; i++)
#pragma unroll
                for (int j = 0; j < 8; j++) {
                    const float* c = acc[i * 8 + j];
                    const int r = (i << 4) + gq;
                    const int b = (j << 3) + (tg << 1);
                    *(float2*)&red[((wid << 5) + r) * RED_PITCH + b]     = make_float2(c[0], c[1]);
                    *(float2*)&red[((wid << 5) + r + 8) * RED_PITCH + b] = make_float2(c[2], c[3]);
                }
            __syncthreads();

#pragma unroll
            for (int pp = 0; pp < 2; pp++) {
                const int jj = pp ? jjB : jjA;
                float gate[4];
#pragma unroll
                for (int q = 0; q < 4; q++) {
                    const int r = (q << 3) + (jj & 7);
                    float s = xq[pp][q];
#pragma unroll
                    for (int w8 = 0; w8 < 8; w8++)
                        s += red[((w8 << 5) + r) * RED_PITCH + bb];
                    gate[q] = s;
                }
                const float cprev = pp ? c1r : c0r;
                float cn = sigf(gate[1]) * cprev + sigf(gate[0]) * tanhf(gate[2]);
                float hn = sigf(gate[3]) * tanhf(cn);
                const float m = mask[t * Bn + bb];
                hn *= m; cn *= m;
                if (pp) c1r = cn; else c0r = cn;
                g_lat[(size_t)t * (Hn * Bn) + ((size_t)(j0 + (jj & 7)) << 6) + bb] = hn;
                if (t == Tn - 1) {
                    out_h[bb * Hn + j0 + (jj & 7)] = hn;
                    out_c[bb * Hn + j0 + (jj & 7)] = cn;
                }
            }
        } else {
#pragma unroll
            for (int pp = 0; pp < 2; pp++) {
                const int jj = (pp ? jjB : jjA) & 7;
                const float cprev = pp ? c1r : c0r;
                float cn = sigf(xq[pp][1]) * cprev + sigf(xq[pp][0]) * tanhf(xq[pp][2]);
                float hn = sigf(xq[pp][3]) * tanhf(cn);
                const float m = mask[t * Bn + bb];
                hn *= m; cn *= m;
                if (pp) c1r = cn; else c0r = cn;
                g_lat[(size_t)t * (Hn * Bn) + ((size_t)(j0 + jj) << 6) + bb] = hn;
            }
        }

        __threadfence();
        __syncthreads();
        if (tid == 0) {
            const unsigned arr = atomicAdd(&g_bar_count, 1);
            if (arr == (unsigned)(nblk - 1)) {
                atomicExch(&g_bar_count, 0);
                __threadfence();
                atomicAdd(&g_bar_gen, 1);
            } else {
                while (*(volatile unsigned*)&g_bar_gen == gen) { }
            }
            gen++;
            __threadfence();
        }
        __syncthreads();
    }
}

// =====================================================================
// Decoder (unchanged)
// =====================================================================
__global__ void __launch_bounds__(256, 1) decoder_kernel(
    const float* __restrict__ Wd, const float* __restrict__ bd,
    const float* __restrict__ mask, float* __restrict__ out_values)
{
    extern __shared__ float dsm[];
    float* Wds  = dsm;
    float* red2 = dsm + 18 * 1024;
    const int t = blockIdx.x;
    const int tid = threadIdx.x;

    for (int i = tid; i < (18 * 1024) / 4; i += 256)
        ((float4*)Wds)[i] = ((const float4*)Wd)[i];
    __syncthreads();

    const int s = tid >> 6;
    const int b = tid & 63;
    float acc[18];
#pragma unroll
    for (int a = 0; a < 18; a++) acc[a] = 0.f;

    const float* L = g_lat + (size_t)t * (Hn * Bn);
    const int hend = (s + 1) << 8;
    for (int h = s << 8; h < hend; h++) {
        const float x = __ldcg(L + (h << 6) + b);
#pragma unroll
        for (int a = 0; a < 18; a++)
            acc[a] = fmaf(x, Wds[a * 1024 + h], acc[a]);
    }
#pragma unroll
    for (int a = 0; a < 18; a++) red2[(s * 64 + b) * 18 + a] = acc[a];
    __syncthreads();

    for (int o = tid; o < 64 * 18; o += 256) {
        const int b2 = o / 18;
        const int a  = o - b2 * 18;
        float v = red2[b2 * 18 + a] + red2[(64 + b2) * 18 + a]
                + red2[(128 + b2) * 18 + a] + red2[(192 + b2) * 18 + a];
        v = (v + bd[a]) * mask[t * Bn + b2];
        out_values[(size_t)t * (Bn * An) + o] = v;
    }
}

// =====================================================================
extern "C" void kernel_launch(void* const* d_in, const int* in_sizes, int n_in,
                              void* d_out, int out_size)
{
    const float* obs   = (const float*)d_in[0];
    const float* mask  = (const float*)d_in[1];
    const float* W_enc = (const float*)d_in[2];
    const float* b_enc = (const float*)d_in[3];
    const float* W_ih  = (const float*)d_in[4];
    const float* b_ih  = (const float*)d_in[5];
    const float* W_hh  = (const float*)d_in[6];
    const float* b_hh  = (const float*)d_in[7];
    const float* W_dec = (const float*)d_in[8];
    const float* b_dec = (const float*)d_in[9];

    float* out        = (float*)d_out;
    float* out_values = out;                                   // [512][64][18]
    float* out_h      = out + (size_t)Tn * Bn * An;            // [64][1024]
    float* out_c      = out_h + (size_t)Bn * Hn;               // [64][1024]

    float *enc_p, *obs_p, *wenc_p, *wih_p;
    cudaGetSymbolAddress((void**)&enc_p,  g_enc);
    cudaGetSymbolAddress((void**)&obs_p,  g_obs_t);
    cudaGetSymbolAddress((void**)&wenc_p, g_wenc_t);
    cudaGetSymbolAddress((void**)&wih_p,  g_wih_t);

    const int gemm_smem = 81920;                               // 4-stage A+B
    const int lstm_smem = (32 * WS_PITCH + 2 * HS_BUF) * 4;    // 205312 B
    cudaFuncSetAttribute(cp_gemm1<OBSn>, cudaFuncAttributeMaxDynamicSharedMemorySize, gemm_smem);
    cudaFuncSetAttribute(g2_gemm,        cudaFuncAttributeMaxDynamicSharedMemorySize, gemm_smem);
    cudaFuncSetAttribute(lstm_kernel,    cudaFuncAttributeMaxDynamicSharedMemorySize, lstm_smem);
    cudaFuncSetAttribute(decoder_kernel, cudaFuncAttributeMaxDynamicSharedMemorySize, 92160);

    // 0) pre-convert GEMM inputs to tf32 bits (rna)
    cvt_tf32_kernel<<<(Mn * OBSn / 4 + 255) / 256, 256>>>((const float4*)obs,   (float4*)obs_p,  Mn * OBSn / 4);
    cvt_tf32_kernel<<<(Hn * OBSn / 4 + 255) / 256, 256>>>((const float4*)W_enc, (float4*)wenc_p, Hn * OBSn / 4);
    cvt_tf32_kernel<<<(G4n * Hn / 4 + 255) / 256, 256>>>((const float4*)W_ih,   (float4*)wih_p,  G4n * Hn / 4);

    // 1) encoded = tf32(relu(obs @ W_enc^T + b_enc)) -> g_enc (tf32 bits)
    dim3 g1(Hn / 128, Mn / 128);
    cp_gemm1<OBSn><<<g1, 256, gemm_smem>>>(obs_p, wenc_p, b_enc, enc_p);

    // 2) x_gates = enc @ W_ih^T + b_ih + b_hh -> g_xg [t][g][b]
    //    (cp.async staging; k-order identical -> bitwise-same x_gates)
    dim3 g2(G4n / 128, Mn / 128);
    g2_gemm<<<g2, 128, gemm_smem>>>(enc_p, wih_p, b_ih, b_hh);

    // 3) persistent LSTM scan -> g_lat, out_h, out_c
    lstm_kernel<<<128, 256, lstm_smem>>>(W_hh, mask, out_h, out_c, 128);

    // 4) decoder -> out_values
    decoder_kernel<<<Tn, 256, 92160>>>(W_dec, b_dec, mask, out_values);
}